// round 8
// baseline (speedup 1.0000x reference)
#include <cuda_runtime.h>
#include <math.h>

#define BATCH 16
#define SEQ   2048
#define HD    64
#define BQ    64
#define BK    64
#define LDSS  68            // smem row stride (floats): float4-aligned, limits conflicts
#define THREADS 256
#define SMEM_BYTES (4 * 64 * LDSS * sizeof(float))   // Qs, Ks, Vs, Ps
#define MASK_ELEMS (16LL * 2048 * 2048)

// 1 => mask stored as int32 elements (bool upcast by harness); 0 => 1 byte per element
__device__ int g_mask_is_wide;

__global__ void detect_mask_kernel(const unsigned char* __restrict__ m)
{
    // One warp. If ALL bytes at offsets !=0 mod 4 in the first 4KB are zero,
    // the mask is int32-layout (little-endian 0/1 ints). With a random 0/1
    // byte mask this misclassifies with probability 2^-3072 (i.e., never).
    const int tid = threadIdx.x;
    int nonzero = 0;
    for (int i = tid; i < 4096; i += 32)
        if ((i & 3) && m[i]) nonzero = 1;
    const unsigned any = __ballot_sync(0xffffffffu, nonzero);
    if (tid == 0) g_mask_is_wide = (any == 0u) ? 1 : 0;
}

__global__ __launch_bounds__(THREADS, 3)
void attn_kernel(const float* __restrict__ q,
                 const float* __restrict__ k,
                 const float* __restrict__ v,
                 const unsigned char* __restrict__ mask,
                 float* __restrict__ out)
{
    extern __shared__ float sm[];
    float* Qs = sm;                     // Qs[kk*LDSS + r]   (transposed)
    float* Ks = sm + 64 * LDSS;         // Ks[kk*LDSS + c]   (transposed)
    float* Vs = sm + 2 * 64 * LDSS;     // Vs[key*LDSS + d]  (natural)
    float* Ps = sm + 3 * 64 * LDSS;     // Ps[key*LDSS + r]

    const int tid = threadIdx.x;
    const int b  = blockIdx.y;
    const int q0 = blockIdx.x * BQ;
    const int wide = g_mask_is_wide;    // uniform; read once

    const int rbase = (tid >> 4) << 2;  // 4 query rows owned by this thread
    const int cbase = (tid & 15) << 2;  // 4 cols (keys / out dims) owned

    // ---- load Q tile, transposed into smem (once) ----
    {
        const int row0 = tid >> 4;
        const int kkb  = (tid & 15) << 2;
        for (int rr = row0; rr < BQ; rr += 16) {
            float4 t = *(const float4*)(q + ((size_t)b * SEQ + q0 + rr) * HD + kkb);
            Qs[(kkb + 0) * LDSS + rr] = t.x;
            Qs[(kkb + 1) * LDSS + rr] = t.y;
            Qs[(kkb + 2) * LDSS + rr] = t.z;
            Qs[(kkb + 3) * LDSS + rr] = t.w;
        }
    }

    float mrun[4], lrun[4], o[4][4];
#pragma unroll
    for (int i = 0; i < 4; i++) {
        mrun[i] = -INFINITY;
        lrun[i] = 0.f;
#pragma unroll
        for (int j = 0; j < 4; j++) o[i][j] = 0.f;
    }

    for (int kt = 0; kt < SEQ / BK; kt++) {
        const int k0 = kt * BK;

        __syncthreads();   // previous-iteration readers of Ks/Vs/Ps are done

        // ---- load K tile transposed + V tile natural ----
        {
            const int row0 = tid >> 4;
            const int kkb  = (tid & 15) << 2;
            for (int rr = row0; rr < BK; rr += 16) {
                float4 t = *(const float4*)(k + ((size_t)b * SEQ + k0 + rr) * HD + kkb);
                Ks[(kkb + 0) * LDSS + rr] = t.x;
                Ks[(kkb + 1) * LDSS + rr] = t.y;
                Ks[(kkb + 2) * LDSS + rr] = t.z;
                Ks[(kkb + 3) * LDSS + rr] = t.w;
            }
            for (int idx = tid; idx < BK * 16; idx += THREADS) {
                const int row = idx >> 4;
                const int db  = (idx & 15) << 2;
                float4 t = *(const float4*)(v + ((size_t)b * SEQ + k0 + row) * HD + db);
                *(float4*)&Vs[row * LDSS + db] = t;
            }
        }
        __syncthreads();

        // ---- S = Q K^T for this thread's 4x4 microtile ----
        float acc[4][4];
#pragma unroll
        for (int i = 0; i < 4; i++)
#pragma unroll
            for (int j = 0; j < 4; j++) acc[i][j] = 0.f;

#pragma unroll 8
        for (int kk = 0; kk < HD; kk++) {
            const float4 a  = *(const float4*)&Qs[kk * LDSS + rbase];
            const float4 bb = *(const float4*)&Ks[kk * LDSS + cbase];
            const float av[4] = {a.x, a.y, a.z, a.w};
            const float bv[4] = {bb.x, bb.y, bb.z, bb.w};
#pragma unroll
            for (int i = 0; i < 4; i++)
#pragma unroll
                for (int j = 0; j < 4; j++)
                    acc[i][j] = fmaf(av[i], bv[j], acc[i][j]);
        }

        // ---- scale (1/8) + mask (True -> 1e-9, faithful to reference) ----
#pragma unroll
        for (int i = 0; i < 4; i++) {
            const size_t e = (size_t)b * SEQ * SEQ
                           + (size_t)(q0 + rbase + i) * SEQ
                           + (size_t)(k0 + cbase);
            int m0, m1, m2, m3;
            if (wide) {               // int32-layout mask (bool upcast by harness)
                const int4 mi = *(const int4*)((const int*)mask + e);
                m0 = mi.x; m1 = mi.y; m2 = mi.z; m3 = mi.w;
            } else {                  // 1-byte bool layout
                const uchar4 mu = *(const uchar4*)(mask + e);
                m0 = mu.x; m1 = mu.y; m2 = mu.z; m3 = mu.w;
            }
            acc[i][0] = m0 ? 1e-9f : acc[i][0] * 0.125f;
            acc[i][1] = m1 ? 1e-9f : acc[i][1] * 0.125f;
            acc[i][2] = m2 ? 1e-9f : acc[i][2] * 0.125f;
            acc[i][3] = m3 ? 1e-9f : acc[i][3] * 0.125f;
        }

        // ---- online softmax: stats reduced over the 16 lanes owning each row ----
#pragma unroll
        for (int i = 0; i < 4; i++) {
            float tm = fmaxf(fmaxf(acc[i][0], acc[i][1]), fmaxf(acc[i][2], acc[i][3]));
#pragma unroll
            for (int off = 1; off < 16; off <<= 1)
                tm = fmaxf(tm, __shfl_xor_sync(0xffffffffu, tm, off));

            const float mnew = fmaxf(mrun[i], tm);
            const float corr = __expf(mrun[i] - mnew);   // first tile: exp(-inf)=0
            mrun[i] = mnew;

            float ssum = 0.f;
#pragma unroll
            for (int j = 0; j < 4; j++) {
                const float p = __expf(acc[i][j] - mnew);
                acc[i][j] = p;
                ssum += p;
            }
#pragma unroll
            for (int off = 1; off < 16; off <<= 1)
                ssum += __shfl_xor_sync(0xffffffffu, ssum, off);

            lrun[i] = lrun[i] * corr + ssum;
#pragma unroll
            for (int j = 0; j < 4; j++) o[i][j] *= corr;

            // stash P transposed for the PV GEMM
#pragma unroll
            for (int j = 0; j < 4; j++)
                Ps[(cbase + j) * LDSS + rbase + i] = acc[i][j];
        }
        __syncthreads();

        // ---- O += P V ----
#pragma unroll 8
        for (int kk = 0; kk < BK; kk++) {
            const float4 p4 = *(const float4*)&Ps[kk * LDSS + rbase];
            const float4 vv = *(const float4*)&Vs[kk * LDSS + cbase];
            const float pv[4]  = {p4.x, p4.y, p4.z, p4.w};
            const float vvv[4] = {vv.x, vv.y, vv.z, vv.w};
#pragma unroll
            for (int i = 0; i < 4; i++)
#pragma unroll
                for (int j = 0; j < 4; j++)
                    o[i][j] = fmaf(pv[i], vvv[j], o[i][j]);
        }
    }

    // ---- epilogue: normalize and store ----
#pragma unroll
    for (int i = 0; i < 4; i++) {
        const float inv = 1.f / lrun[i];
        float4 r;
        r.x = o[i][0] * inv;
        r.y = o[i][1] * inv;
        r.z = o[i][2] * inv;
        r.w = o[i][3] * inv;
        *(float4*)(out + ((size_t)b * SEQ + q0 + rbase + i) * HD + cbase) = r;
    }
}

extern "C" void kernel_launch(void* const* d_in, const int* in_sizes, int n_in,
                              void* d_out, int out_size)
{
    (void)out_size;
    // Locate the mask by element count (robust to metadata ordering);
    // the remaining three float32 inputs keep their relative order: q, k, v.
    int mask_idx = -1;
    for (int i = 0; i < n_in; i++)
        if ((long long)in_sizes[i] == MASK_ELEMS) { mask_idx = i; break; }
    if (mask_idx < 0) mask_idx = 3;   // fallback: insertion order

    const float* qkv[3];
    int nq = 0;
    for (int i = 0; i < n_in && nq < 3; i++)
        if (i != mask_idx) qkv[nq++] = (const float*)d_in[i];

    const float* q = qkv[0];
    const float* k = qkv[1];
    const float* v = qkv[2];
    const unsigned char* mask = (const unsigned char*)d_in[mask_idx];
    float* out = (float*)d_out;

    cudaFuncSetAttribute(attn_kernel, cudaFuncAttributeMaxDynamicSharedMemorySize,
                         (int)SMEM_BYTES);

    detect_mask_kernel<<<1, 32>>>(mask);

    dim3 grid(SEQ / BQ, BATCH);
    attn_kernel<<<grid, THREADS, SMEM_BYTES>>>(q, k, v, mask, out);
}

// round 9
// speedup vs baseline: 1.8039x; 1.8039x over previous
#include <cuda_runtime.h>
#include <math.h>

#define BATCH 16
#define SEQ   2048
#define HD    64
#define BQ    128
#define BK    128
#define THREADS 256
#define LQ 132        // stride (floats) for Qs/Ks rows: [hd][row/key], padded
#define LV 68         // stride for Vs: [key][dim]
#define LP 132        // stride for Ps: [row][key], padded

// float offsets in dynamic smem
#define QS_OFF 0
#define KS_OFF (64 * LQ)                       // 8448
#define VS_OFF (KS_OFF + 64 * LQ)              // 16896
#define PS_OFF (VS_OFF + BK * LV)              // 25600
#define SMEM_FLOATS (PS_OFF + BQ * LP)         // 42496
#define SMEM_BYTES (SMEM_FLOATS * sizeof(float))   // 169984 B

#define MASK_ELEMS (16LL * 2048 * 2048)

// 1 => mask stored as int32 elements (bool upcast by harness); 0 => 1 byte per element
__device__ int g_mask_is_wide;

__global__ void detect_mask_kernel(const unsigned char* __restrict__ m)
{
    const int tid = threadIdx.x;
    int nonzero = 0;
    for (int i = tid; i < 4096; i += 32)
        if ((i & 3) && m[i]) nonzero = 1;
    const unsigned any = __ballot_sync(0xffffffffu, nonzero);
    if (tid == 0) g_mask_is_wide = (any == 0u) ? 1 : 0;
}

__global__ __launch_bounds__(THREADS, 1)
void attn_kernel(const float* __restrict__ q,
                 const float* __restrict__ k,
                 const float* __restrict__ v,
                 const unsigned char* __restrict__ mask,
                 float* __restrict__ out)
{
    extern __shared__ float sm[];
    float* Qs = sm + QS_OFF;   // Qs[kk*LQ + r]   (transposed)
    float* Ks = sm + KS_OFF;   // Ks[kk*LQ + c]   (transposed)
    float* Vs = sm + VS_OFF;   // Vs[key*LV + d]  (natural)
    float* Ps = sm + PS_OFF;   // Ps[r*LP + key]  (natural)

    const int tid = threadIdx.x;
    const int b  = blockIdx.y;
    const int q0 = blockIdx.x * BQ;
    const int wide = g_mask_is_wide;

    const int tx = tid & 15;
    const int ty = tid >> 4;
    const int rbase = ty * 8;   // 8 query rows owned
    const int cbase = tx * 8;   // 8 key cols owned (S tile)
    const int dbase = tx * 4;   // 4 out dims owned (O tile)

    // ---- load Q tile, transposed into smem (once): 128 rows x 64 hd ----
    for (int t = tid; t < BQ * 16; t += THREADS) {
        const int row = t >> 4;
        const int kkb = (t & 15) << 2;
        float4 x = *(const float4*)(q + ((size_t)b * SEQ + q0 + row) * HD + kkb);
        Qs[(kkb + 0) * LQ + row] = x.x;
        Qs[(kkb + 1) * LQ + row] = x.y;
        Qs[(kkb + 2) * LQ + row] = x.z;
        Qs[(kkb + 3) * LQ + row] = x.w;
    }

    float mrun[8], lrun[8], o[8][4];
#pragma unroll
    for (int i = 0; i < 8; i++) {
        mrun[i] = -INFINITY;
        lrun[i] = 0.f;
#pragma unroll
        for (int d = 0; d < 4; d++) o[i][d] = 0.f;
    }

    for (int kt = 0; kt < SEQ / BK; kt++) {
        const int k0 = kt * BK;

        __syncthreads();   // previous iteration's readers of Ks/Vs/Ps done

        // ---- K tile transposed (scatter) + V tile natural ----
        for (int t = tid; t < BK * 16; t += THREADS) {
            const int row = t >> 4;          // key index
            const int kkb = (t & 15) << 2;
            float4 x = *(const float4*)(k + ((size_t)b * SEQ + k0 + row) * HD + kkb);
            Ks[(kkb + 0) * LQ + row] = x.x;
            Ks[(kkb + 1) * LQ + row] = x.y;
            Ks[(kkb + 2) * LQ + row] = x.z;
            Ks[(kkb + 3) * LQ + row] = x.w;
        }
        for (int t = tid; t < BK * 16; t += THREADS) {
            const int row = t >> 4;
            const int db  = (t & 15) << 2;
            float4 x = *(const float4*)(v + ((size_t)b * SEQ + k0 + row) * HD + db);
            *(float4*)&Vs[row * LV + db] = x;
        }
        __syncthreads();

        // ---- S = Q K^T : 8x8 microtile ----
        float acc[8][8];
#pragma unroll
        for (int i = 0; i < 8; i++)
#pragma unroll
            for (int j = 0; j < 8; j++) acc[i][j] = 0.f;

#pragma unroll 4
        for (int kk = 0; kk < HD; kk++) {
            const float4 a0 = *(const float4*)&Qs[kk * LQ + rbase];
            const float4 a1 = *(const float4*)&Qs[kk * LQ + rbase + 4];
            const float4 b0 = *(const float4*)&Ks[kk * LQ + cbase];
            const float4 b1 = *(const float4*)&Ks[kk * LQ + cbase + 4];
            const float av[8] = {a0.x, a0.y, a0.z, a0.w, a1.x, a1.y, a1.z, a1.w};
            const float bv[8] = {b0.x, b0.y, b0.z, b0.w, b1.x, b1.y, b1.z, b1.w};
#pragma unroll
            for (int i = 0; i < 8; i++)
#pragma unroll
                for (int j = 0; j < 8; j++)
                    acc[i][j] = fmaf(av[i], bv[j], acc[i][j]);
        }

        // ---- scale (1/8) + mask (True -> 1e-9) ----
#pragma unroll
        for (int i = 0; i < 8; i++) {
            const size_t e = (size_t)b * SEQ * SEQ
                           + (size_t)(q0 + rbase + i) * SEQ
                           + (size_t)(k0 + cbase);
            int m[8];
            if (wide) {
                const int4 w0 = *(const int4*)((const int*)mask + e);
                const int4 w1 = *(const int4*)((const int*)mask + e + 4);
                m[0]=w0.x; m[1]=w0.y; m[2]=w0.z; m[3]=w0.w;
                m[4]=w1.x; m[5]=w1.y; m[6]=w1.z; m[7]=w1.w;
            } else {
                const uchar4 u0 = *(const uchar4*)(mask + e);
                const uchar4 u1 = *(const uchar4*)(mask + e + 4);
                m[0]=u0.x; m[1]=u0.y; m[2]=u0.z; m[3]=u0.w;
                m[4]=u1.x; m[5]=u1.y; m[6]=u1.z; m[7]=u1.w;
            }
#pragma unroll
            for (int j = 0; j < 8; j++)
                acc[i][j] = m[j] ? 1e-9f : acc[i][j] * 0.125f;
        }

        // ---- online softmax per row (16 lanes own each row) ----
#pragma unroll
        for (int i = 0; i < 8; i++) {
            float tm = acc[i][0];
#pragma unroll
            for (int j = 1; j < 8; j++) tm = fmaxf(tm, acc[i][j]);
#pragma unroll
            for (int off = 1; off < 16; off <<= 1)
                tm = fmaxf(tm, __shfl_xor_sync(0xffffffffu, tm, off));

            const float mnew = fmaxf(mrun[i], tm);
            const float corr = __expf(mrun[i] - mnew);   // first tile: exp(-inf)=0
            mrun[i] = mnew;

            float ssum = 0.f;
#pragma unroll
            for (int j = 0; j < 8; j++) {
                const float p = __expf(acc[i][j] - mnew);
                acc[i][j] = p;
                ssum += p;
            }
#pragma unroll
            for (int off = 1; off < 16; off <<= 1)
                ssum += __shfl_xor_sync(0xffffffffu, ssum, off);

            lrun[i] = lrun[i] * corr + ssum;
#pragma unroll
            for (int d = 0; d < 4; d++) o[i][d] *= corr;

            // P natural layout: row-major, padded stride
            float4 p0 = make_float4(acc[i][0], acc[i][1], acc[i][2], acc[i][3]);
            float4 p1 = make_float4(acc[i][4], acc[i][5], acc[i][6], acc[i][7]);
            *(float4*)&Ps[(rbase + i) * LP + cbase]     = p0;
            *(float4*)&Ps[(rbase + i) * LP + cbase + 4] = p1;
        }
        __syncthreads();

        // ---- O += P V : process 4 keys per step ----
#pragma unroll 2
        for (int kb = 0; kb < BK; kb += 4) {
            float4 pv[8];
#pragma unroll
            for (int i = 0; i < 8; i++)
                pv[i] = *(const float4*)&Ps[(rbase + i) * LP + kb];
            float4 vv[4];
#pragma unroll
            for (int mI = 0; mI < 4; mI++)
                vv[mI] = *(const float4*)&Vs[(kb + mI) * LV + dbase];
#pragma unroll
            for (int i = 0; i < 8; i++) {
                o[i][0] = fmaf(pv[i].x, vv[0].x, o[i][0]);
                o[i][1] = fmaf(pv[i].x, vv[0].y, o[i][1]);
                o[i][2] = fmaf(pv[i].x, vv[0].z, o[i][2]);
                o[i][3] = fmaf(pv[i].x, vv[0].w, o[i][3]);
                o[i][0] = fmaf(pv[i].y, vv[1].x, o[i][0]);
                o[i][1] = fmaf(pv[i].y, vv[1].y, o[i][1]);
                o[i][2] = fmaf(pv[i].y, vv[1].z, o[i][2]);
                o[i][3] = fmaf(pv[i].y, vv[1].w, o[i][3]);
                o[i][0] = fmaf(pv[i].z, vv[2].x, o[i][0]);
                o[i][1] = fmaf(pv[i].z, vv[2].y, o[i][1]);
                o[i][2] = fmaf(pv[i].z, vv[2].z, o[i][2]);
                o[i][3] = fmaf(pv[i].z, vv[2].w, o[i][3]);
                o[i][0] = fmaf(pv[i].w, vv[3].x, o[i][0]);
                o[i][1] = fmaf(pv[i].w, vv[3].y, o[i][1]);
                o[i][2] = fmaf(pv[i].w, vv[3].z, o[i][2]);
                o[i][3] = fmaf(pv[i].w, vv[3].w, o[i][3]);
            }
        }
    }

    // ---- epilogue: normalize and store ----
#pragma unroll
    for (int i = 0; i < 8; i++) {
        const float inv = 1.f / lrun[i];
        float4 r;
        r.x = o[i][0] * inv;
        r.y = o[i][1] * inv;
        r.z = o[i][2] * inv;
        r.w = o[i][3] * inv;
        *(float4*)(out + ((size_t)b * SEQ + q0 + rbase + i) * HD + dbase) = r;
    }
}

extern "C" void kernel_launch(void* const* d_in, const int* in_sizes, int n_in,
                              void* d_out, int out_size)
{
    (void)out_size;
    // Locate the mask by element count (robust to metadata ordering);
    // remaining three float32 inputs keep relative order: q, k, v.
    int mask_idx = -1;
    for (int i = 0; i < n_in; i++)
        if ((long long)in_sizes[i] == MASK_ELEMS) { mask_idx = i; break; }
    if (mask_idx < 0) mask_idx = 3;

    const float* qkv[3];
    int nq = 0;
    for (int i = 0; i < n_in && nq < 3; i++)
        if (i != mask_idx) qkv[nq++] = (const float*)d_in[i];

    const float* q = qkv[0];
    const float* k = qkv[1];
    const float* v = qkv[2];
    const unsigned char* mask = (const unsigned char*)d_in[mask_idx];
    float* out = (float*)d_out;

    cudaFuncSetAttribute(attn_kernel, cudaFuncAttributeMaxDynamicSharedMemorySize,
                         (int)SMEM_BYTES);

    detect_mask_kernel<<<1, 32>>>(mask);

    dim3 grid(SEQ / BQ, BATCH);
    attn_kernel<<<grid, THREADS, SMEM_BYTES>>>(q, k, v, mask, out);
}

// round 14
// speedup vs baseline: 3.3750x; 1.8710x over previous
#include <cuda_runtime.h>
#include <cuda_bf16.h>
#include <math.h>

#define BATCH 16
#define SEQ   2048
#define HD    64
#define BQ    128
#define BK    64
#define THREADS 256
#define LDB   72              // bf16 smem row stride: 144B => conflict-free frag loads
#define MASK_ELEMS (16LL * 2048 * 2048)

// 1 => mask stored as int32 elements (bool upcast by harness); 0 => byte mask
__device__ int g_mask_is_wide;

__global__ void detect_mask_kernel(const unsigned char* __restrict__ m)
{
    const int tid = threadIdx.x;
    int nonzero = 0;
    for (int i = tid; i < 4096; i += 32)
        if ((i & 3) && m[i]) nonzero = 1;
    const unsigned any = __ballot_sync(0xffffffffu, nonzero);
    if (tid == 0) g_mask_is_wide = (any == 0u) ? 1 : 0;
}

// pack two floats into bf16x2: x -> low half (lower k index), y -> high half
__device__ __forceinline__ unsigned pack2(float x, float y)
{
    unsigned r;
    asm("cvt.rn.bf16x2.f32 %0, %1, %2;" : "=r"(r) : "f"(y), "f"(x));
    return r;
}
__device__ __forceinline__ void split2(float x, float y, unsigned& h, unsigned& l)
{
    h = pack2(x, y);
    const float hx = __uint_as_float(h << 16);
    const float hy = __uint_as_float(h & 0xffff0000u);
    l = pack2(x - hx, y - hy);
}

__device__ __forceinline__ void mma_bf16(float d[4], const unsigned a[4],
                                         unsigned b0, unsigned b1)
{
    asm("mma.sync.aligned.m16n8k16.row.col.f32.bf16.bf16.f32 "
        "{%0,%1,%2,%3},{%4,%5,%6,%7},{%8,%9},{%0,%1,%2,%3};"
        : "+f"(d[0]), "+f"(d[1]), "+f"(d[2]), "+f"(d[3])
        : "r"(a[0]), "r"(a[1]), "r"(a[2]), "r"(a[3]), "r"(b0), "r"(b1));
}

__global__ __launch_bounds__(THREADS, 1)
void attn_kernel(const float* __restrict__ q,
                 const float* __restrict__ k,
                 const float* __restrict__ v,
                 const unsigned char* __restrict__ mask,
                 float* __restrict__ out)
{
    __shared__ __align__(16) __nv_bfloat16 Khi[BK][LDB];  // [key][d]
    __shared__ __align__(16) __nv_bfloat16 Klo[BK][LDB];
    __shared__ __align__(16) __nv_bfloat16 Vhi[HD][LDB];  // [d][key] (transposed)
    __shared__ __align__(16) __nv_bfloat16 Vlo[HD][LDB];

    const int tid  = threadIdx.x;
    const int warp = tid >> 5;
    const int lane = tid & 31;
    const int g    = lane >> 2;     // 0..7
    const int c    = lane & 3;      // 0..3
    const int b    = blockIdx.y;
    const int q0   = blockIdx.x * BQ;
    const int wide = g_mask_is_wide;

    const int row_lo = warp * 16 + g;      // within CTA tile
    const int row_hi = row_lo + 8;

    // ---- Q fragments in registers (hi/lo bf16 split), loaded once ----
    unsigned qh[4][4], ql[4][4];           // [kstep s][a-reg]
    {
        const float* qlo_p = q + ((size_t)b * SEQ + q0 + row_lo) * HD;
        const float* qhi_p = qlo_p + 8 * HD;
#pragma unroll
        for (int s = 0; s < 4; s++) {
            float2 f0 = *(const float2*)(qlo_p + 16 * s + 2 * c);
            float2 f1 = *(const float2*)(qhi_p + 16 * s + 2 * c);
            float2 f2 = *(const float2*)(qlo_p + 16 * s + 2 * c + 8);
            float2 f3 = *(const float2*)(qhi_p + 16 * s + 2 * c + 8);
            split2(f0.x, f0.y, qh[s][0], ql[s][0]);
            split2(f1.x, f1.y, qh[s][1], ql[s][1]);
            split2(f2.x, f2.y, qh[s][2], ql[s][2]);
            split2(f3.x, f3.y, qh[s][3], ql[s][3]);
        }
    }

    float o[8][4];                          // O fragments [d-tile][reg]
#pragma unroll
    for (int t = 0; t < 8; t++)
#pragma unroll
        for (int r = 0; r < 4; r++) o[t][r] = 0.f;

    float mr_lo = -INFINITY, mr_hi = -INFINITY, l_lo = 0.f, l_hi = 0.f;

    // ---- cooperative K/V gmem prefetch (tile 0) ----
    const int krow = tid >> 2;              // 0..63
    const int cb   = (tid & 3) * 16;        // 0,16,32,48
    float4 kx[4], vx[4];
    {
        const float* kp = k + ((size_t)b * SEQ + 0 + krow) * HD + cb;
        const float* vp = v + ((size_t)b * SEQ + 0 + krow) * HD + cb;
#pragma unroll
        for (int j = 0; j < 4; j++) { kx[j] = *(const float4*)(kp + 4 * j);
                                      vx[j] = *(const float4*)(vp + 4 * j); }
    }

    const size_t mrow_lo_base = ((size_t)b * SEQ + q0 + row_lo) * SEQ + 2 * c;
    const size_t mrow_hi_base = mrow_lo_base + 8 * SEQ;

    for (int kt = 0; kt < SEQ / BK; kt++) {
        const int k0 = kt * BK;

        __syncthreads();   // previous tile's smem readers are done

        // ---- store prefetched K (natural) and V (transposed) as bf16 hi/lo ----
#pragma unroll
        for (int j = 0; j < 4; j++) {
            const float4 f = kx[j];
            unsigned h01, l01, h23, l23;
            split2(f.x, f.y, h01, l01);
            split2(f.z, f.w, h23, l23);
            *(uint2*)&Khi[krow][cb + 4 * j] = make_uint2(h01, h23);
            *(uint2*)&Klo[krow][cb + 4 * j] = make_uint2(l01, l23);
        }
#pragma unroll
        for (int j = 0; j < 4; j++) {
            const float4 f = vx[j];
            const int d0 = cb + 4 * j;
            const float e[4] = {f.x, f.y, f.z, f.w};
#pragma unroll
            for (int ei = 0; ei < 4; ei++) {
                const __nv_bfloat16 hb = __float2bfloat16(e[ei]);
                const float lo = e[ei] - __bfloat162float(hb);
                Vhi[d0 + ei][krow] = hb;
                Vlo[d0 + ei][krow] = __float2bfloat16(lo);
            }
        }
        __syncthreads();

        // ---- prefetch next tile's K/V ----
        {
            const int kn = (kt + 1 < SEQ / BK) ? (k0 + BK) : k0;
            const float* kp = k + ((size_t)b * SEQ + kn + krow) * HD + cb;
            const float* vp = v + ((size_t)b * SEQ + kn + krow) * HD + cb;
#pragma unroll
            for (int j = 0; j < 4; j++) { kx[j] = *(const float4*)(kp + 4 * j);
                                          vx[j] = *(const float4*)(vp + 4 * j); }
        }

        // ---- mask loads (cover latency under the QK mmas) ----
        int mA[8], mB[8], mC[8], mD[8];     // rows lo/hi, cols 2c / 2c+1
        if (wide) {
            const int* mi = (const int*)mask;
#pragma unroll
            for (int T = 0; T < 8; T++) {
                const int2 u = *(const int2*)(mi + mrow_lo_base + k0 + 8 * T);
                const int2 w = *(const int2*)(mi + mrow_hi_base + k0 + 8 * T);
                mA[T] = u.x; mB[T] = u.y; mC[T] = w.x; mD[T] = w.y;
            }
        } else {
#pragma unroll
            for (int T = 0; T < 8; T++) {
                const uchar2 u = *(const uchar2*)(mask + mrow_lo_base + k0 + 8 * T);
                const uchar2 w = *(const uchar2*)(mask + mrow_hi_base + k0 + 8 * T);
                mA[T] = u.x; mB[T] = u.y; mC[T] = w.x; mD[T] = w.y;
            }
        }

        // ---- S = Q K^T via 3x split-bf16 mma ----
        float sacc[8][4];
#pragma unroll
        for (int T = 0; T < 8; T++)
#pragma unroll
            for (int r = 0; r < 4; r++) sacc[T][r] = 0.f;

#pragma unroll
        for (int T = 0; T < 8; T++) {
#pragma unroll
            for (int s = 0; s < 4; s++) {
                const unsigned bh0 = *(const unsigned*)&Khi[8 * T + g][16 * s + 2 * c];
                const unsigned bh1 = *(const unsigned*)&Khi[8 * T + g][16 * s + 2 * c + 8];
                const unsigned bl0 = *(const unsigned*)&Klo[8 * T + g][16 * s + 2 * c];
                const unsigned bl1 = *(const unsigned*)&Klo[8 * T + g][16 * s + 2 * c + 8];
                mma_bf16(sacc[T], qh[s], bh0, bh1);
                mma_bf16(sacc[T], qh[s], bl0, bl1);
                mma_bf16(sacc[T], ql[s], bh0, bh1);
            }
        }

        // ---- scale (1/8) + mask (True -> 1e-9) ----
#pragma unroll
        for (int T = 0; T < 8; T++) {
            sacc[T][0] = mA[T] ? 1e-9f : sacc[T][0] * 0.125f;
            sacc[T][1] = mB[T] ? 1e-9f : sacc[T][1] * 0.125f;
            sacc[T][2] = mC[T] ? 1e-9f : sacc[T][2] * 0.125f;
            sacc[T][3] = mD[T] ? 1e-9f : sacc[T][3] * 0.125f;
        }

        // ---- online softmax (row stats across the 4-lane quad) ----
        float tmx_lo = sacc[0][0], tmx_hi = sacc[0][2];
#pragma unroll
        for (int T = 0; T < 8; T++) {
            tmx_lo = fmaxf(tmx_lo, fmaxf(sacc[T][0], sacc[T][1]));
            tmx_hi = fmaxf(tmx_hi, fmaxf(sacc[T][2], sacc[T][3]));
        }
#pragma unroll
        for (int off = 1; off < 4; off <<= 1) {
            tmx_lo = fmaxf(tmx_lo, __shfl_xor_sync(0xffffffffu, tmx_lo, off));
            tmx_hi = fmaxf(tmx_hi, __shfl_xor_sync(0xffffffffu, tmx_hi, off));
        }

        const float mn_lo = fmaxf(mr_lo, tmx_lo);
        const float mn_hi = fmaxf(mr_hi, tmx_hi);
        const float cr_lo = __expf(mr_lo - mn_lo);   // first tile: exp(-inf)=0
        const float cr_hi = __expf(mr_hi - mn_hi);
        mr_lo = mn_lo; mr_hi = mn_hi;

#pragma unroll
        for (int t = 0; t < 8; t++) {
            o[t][0] *= cr_lo; o[t][1] *= cr_lo;
            o[t][2] *= cr_hi; o[t][3] *= cr_hi;
        }

        float sum_lo = 0.f, sum_hi = 0.f;
        unsigned phA[8], phB[8], plA[8], plB[8];     // P frags: rows g / g+8
#pragma unroll
        for (int T = 0; T < 8; T++) {
            const float p0 = __expf(sacc[T][0] - mn_lo);
            const float p1 = __expf(sacc[T][1] - mn_lo);
            const float p2 = __expf(sacc[T][2] - mn_hi);
            const float p3 = __expf(sacc[T][3] - mn_hi);
            sum_lo += p0 + p1;
            sum_hi += p2 + p3;
            split2(p0, p1, phA[T], plA[T]);
            split2(p2, p3, phB[T], plB[T]);
        }
#pragma unroll
        for (int off = 1; off < 4; off <<= 1) {
            sum_lo += __shfl_xor_sync(0xffffffffu, sum_lo, off);
            sum_hi += __shfl_xor_sync(0xffffffffu, sum_hi, off);
        }
        l_lo = l_lo * cr_lo + sum_lo;
        l_hi = l_hi * cr_hi + sum_hi;

        // ---- O += P V via 3x split-bf16 mma (P fragments stay in registers) ----
#pragma unroll
        for (int t = 0; t < 8; t++) {
#pragma unroll
            for (int s = 0; s < 4; s++) {
                const unsigned vh0 = *(const unsigned*)&Vhi[8 * t + g][16 * s + 2 * c];
                const unsigned vh1 = *(const unsigned*)&Vhi[8 * t + g][16 * s + 2 * c + 8];
                const unsigned vl0 = *(const unsigned*)&Vlo[8 * t + g][16 * s + 2 * c];
                const unsigned vl1 = *(const unsigned*)&Vlo[8 * t + g][16 * s + 2 * c + 8];
                const unsigned ah[4] = {phA[2 * s], phB[2 * s], phA[2 * s + 1], phB[2 * s + 1]};
                const unsigned al[4] = {plA[2 * s], plB[2 * s], plA[2 * s + 1], plB[2 * s + 1]};
                mma_bf16(o[t], ah, vh0, vh1);
                mma_bf16(o[t], ah, vl0, vl1);
                mma_bf16(o[t], al, vh0, vh1);
            }
        }
    }

    // ---- epilogue: normalize and store ----
    const float inv_lo = 1.f / l_lo;
    const float inv_hi = 1.f / l_hi;
    float* olo_p = out + ((size_t)b * SEQ + q0 + row_lo) * HD;
    float* ohi_p = olo_p + 8 * HD;
#pragma unroll
    for (int t = 0; t < 8; t++) {
        *(float2*)(olo_p + 8 * t + 2 * c) = make_float2(o[t][0] * inv_lo, o[t][1] * inv_lo);
        *(float2*)(ohi_p + 8 * t + 2 * c) = make_float2(o[t][2] * inv_hi, o[t][3] * inv_hi);
    }
}

extern "C" void kernel_launch(void* const* d_in, const int* in_sizes, int n_in,
                              void* d_out, int out_size)
{
    (void)out_size;
    int mask_idx = -1;
    for (int i = 0; i < n_in; i++)
        if ((long long)in_sizes[i] == MASK_ELEMS) { mask_idx = i; break; }
    if (mask_idx < 0) mask_idx = 3;

    const float* qkv[3];
    int nq = 0;
    for (int i = 0; i < n_in && nq < 3; i++)
        if (i != mask_idx) qkv[nq++] = (const float*)d_in[i];

    const float* q = qkv[0];
    const float* k = qkv[1];
    const float* v = qkv[2];
    const unsigned char* mask = (const unsigned char*)d_in[mask_idx];
    float* out = (float*)d_out;

    detect_mask_kernel<<<1, 32>>>(mask);

    dim3 grid(SEQ / BQ, BATCH);
    attn_kernel<<<grid, THREADS>>>(q, k, v, mask, out);
}

// round 16
// speedup vs baseline: 4.4153x; 1.3083x over previous
#include <cuda_runtime.h>
#include <cuda_bf16.h>
#include <math.h>

#define BATCH 16
#define SEQ   2048
#define HD    64
#define BQ    128
#define BK    64
#define THREADS 256
#define LDB   72              // bf16 smem row stride: 144B => conflict-free ldmatrix
#define MASK_ELEMS (16LL * 2048 * 2048)

// per-stage smem layout (bf16 elements)
#define KHI_OFF 0
#define KLO_OFF (64 * LDB)
#define VHI_OFF (2 * 64 * LDB)
#define VLO_OFF (3 * 64 * LDB)
#define STAGE_ELEMS (4 * 64 * LDB)
#define SMEM_BYTES (2 * STAGE_ELEMS * 2)   // 2 stages, bf16  = 73728 B

// 1 => mask stored as int32 elements (bool upcast by harness); 0 => byte mask
__device__ int g_mask_is_wide;

__global__ void detect_mask_kernel(const unsigned char* __restrict__ m)
{
    const int tid = threadIdx.x;
    int nonzero = 0;
    for (int i = tid; i < 4096; i += 32)
        if ((i & 3) && m[i]) nonzero = 1;
    const unsigned any = __ballot_sync(0xffffffffu, nonzero);
    if (tid == 0) g_mask_is_wide = (any == 0u) ? 1 : 0;
}

// pack two floats into bf16x2: x -> low half (lower k index), y -> high half
__device__ __forceinline__ unsigned pack2(float x, float y)
{
    unsigned r;
    asm("cvt.rn.bf16x2.f32 %0, %1, %2;" : "=r"(r) : "f"(y), "f"(x));
    return r;
}
__device__ __forceinline__ void split2(float x, float y, unsigned& h, unsigned& l)
{
    h = pack2(x, y);
    const float hx = __uint_as_float(h << 16);
    const float hy = __uint_as_float(h & 0xffff0000u);
    l = pack2(x - hx, y - hy);
}

__device__ __forceinline__ void mma_bf16(float d[4], const unsigned a[4],
                                         unsigned b0, unsigned b1)
{
    asm("mma.sync.aligned.m16n8k16.row.col.f32.bf16.bf16.f32 "
        "{%0,%1,%2,%3},{%4,%5,%6,%7},{%8,%9},{%0,%1,%2,%3};"
        : "+f"(d[0]), "+f"(d[1]), "+f"(d[2]), "+f"(d[3])
        : "r"(a[0]), "r"(a[1]), "r"(a[2]), "r"(a[3]), "r"(b0), "r"(b1));
}

__device__ __forceinline__ void ldsm4(unsigned& r0, unsigned& r1,
                                      unsigned& r2, unsigned& r3, unsigned a)
{
    asm volatile("ldmatrix.sync.aligned.m8n8.x4.shared.b16 {%0,%1,%2,%3},[%4];"
                 : "=r"(r0), "=r"(r1), "=r"(r2), "=r"(r3) : "r"(a));
}
__device__ __forceinline__ void ldsm4t(unsigned& r0, unsigned& r1,
                                       unsigned& r2, unsigned& r3, unsigned a)
{
    asm volatile("ldmatrix.sync.aligned.m8n8.x4.trans.shared.b16 {%0,%1,%2,%3},[%4];"
                 : "=r"(r0), "=r"(r1), "=r"(r2), "=r"(r3) : "r"(a));
}

__global__ __launch_bounds__(THREADS, 1)
void attn_kernel(const float* __restrict__ q,
                 const float* __restrict__ k,
                 const float* __restrict__ v,
                 const unsigned char* __restrict__ mask,
                 float* __restrict__ out)
{
    extern __shared__ __align__(16) __nv_bfloat16 smbuf[];

    const int tid  = threadIdx.x;
    const int warp = tid >> 5;
    const int lane = tid & 31;
    const int g    = lane >> 2;     // 0..7
    const int c    = lane & 3;      // 0..3
    const int b    = blockIdx.y;
    const int q0   = blockIdx.x * BQ;
    const int wide = g_mask_is_wide;

    const int row_lo = warp * 16 + g;

    const unsigned sm_base = (unsigned)__cvta_generic_to_shared(smbuf);
    const int r8    = lane & 7;
    const int matid = lane >> 3;
    // QK (non-trans): mat0/1 -> T0 cols 0/8 ; mat2/3 -> T1 cols 0/8
    const unsigned qk_lane = 2u * ((unsigned)(8 * (matid >> 1) + r8) * LDB + 8 * (matid & 1));
    // PV (trans): mat0/1 -> t0 rows 0/8 ; mat2/3 -> t1 rows 0/8
    const unsigned pv_lane = 2u * ((unsigned)(8 * (matid & 1) + r8) * LDB + 8 * (matid >> 1));

    // ---- Q fragments in registers (hi/lo bf16 split), loaded once ----
    unsigned qh[4][4], ql[4][4];
    {
        const float* qlo_p = q + ((size_t)b * SEQ + q0 + row_lo) * HD;
        const float* qhi_p = qlo_p + 8 * HD;
#pragma unroll
        for (int s = 0; s < 4; s++) {
            float2 f0 = *(const float2*)(qlo_p + 16 * s + 2 * c);
            float2 f1 = *(const float2*)(qhi_p + 16 * s + 2 * c);
            float2 f2 = *(const float2*)(qlo_p + 16 * s + 2 * c + 8);
            float2 f3 = *(const float2*)(qhi_p + 16 * s + 2 * c + 8);
            split2(f0.x, f0.y, qh[s][0], ql[s][0]);
            split2(f1.x, f1.y, qh[s][1], ql[s][1]);
            split2(f2.x, f2.y, qh[s][2], ql[s][2]);
            split2(f3.x, f3.y, qh[s][3], ql[s][3]);
        }
    }

    float o[8][4];
#pragma unroll
    for (int t = 0; t < 8; t++)
#pragma unroll
        for (int r = 0; r < 4; r++) o[t][r] = 0.f;

    float mr_lo = -INFINITY, mr_hi = -INFINITY, l_lo = 0.f, l_hi = 0.f;

    const int krow = tid >> 2;              // 0..63
    const int cb   = (tid & 3) * 16;        // 0,16,32,48

    // store a prefetched K/V tile (registers) into smem stage st as split bf16
    auto store_tile = [&](int st, const float4* kx, const float4* vx) {
        __nv_bfloat16* stage = smbuf + st * STAGE_ELEMS;
#pragma unroll
        for (int j = 0; j < 4; j++) {
            unsigned h01, l01, h23, l23;
            split2(kx[j].x, kx[j].y, h01, l01);
            split2(kx[j].z, kx[j].w, h23, l23);
            *(uint2*)&stage[KHI_OFF + krow * LDB + cb + 4 * j] = make_uint2(h01, h23);
            *(uint2*)&stage[KLO_OFF + krow * LDB + cb + 4 * j] = make_uint2(l01, l23);
        }
#pragma unroll
        for (int j = 0; j < 4; j++) {
            unsigned h01, l01, h23, l23;
            split2(vx[j].x, vx[j].y, h01, l01);
            split2(vx[j].z, vx[j].w, h23, l23);
            *(uint2*)&stage[VHI_OFF + krow * LDB + cb + 4 * j] = make_uint2(h01, h23);
            *(uint2*)&stage[VLO_OFF + krow * LDB + cb + 4 * j] = make_uint2(l01, l23);
        }
    };

    // ---- prefetch + store tile 0 into stage 0 ----
    float4 kx[4], vx[4];
    {
        const float* kp = k + ((size_t)b * SEQ + krow) * HD + cb;
        const float* vp = v + ((size_t)b * SEQ + krow) * HD + cb;
#pragma unroll
        for (int j = 0; j < 4; j++) { kx[j] = *(const float4*)(kp + 4 * j);
                                      vx[j] = *(const float4*)(vp + 4 * j); }
    }
    store_tile(0, kx, vx);

    const size_t mrow_lo_base = ((size_t)b * SEQ + q0 + row_lo) * SEQ + 2 * c;
    const size_t mrow_hi_base = mrow_lo_base + 8 * SEQ;

    for (int kt = 0; kt < SEQ / BK; kt++) {
        const int k0 = kt * BK;
        const int st = kt & 1;
        const unsigned stage_b = sm_base + (unsigned)(st * STAGE_ELEMS * 2);
        const unsigned khi_b = stage_b + 2u * KHI_OFF + qk_lane;
        const unsigned klo_b = stage_b + 2u * KLO_OFF + qk_lane;
        const unsigned vhi_b = stage_b + 2u * VHI_OFF + pv_lane;
        const unsigned vlo_b = stage_b + 2u * VLO_OFF + pv_lane;

        __syncthreads();   // stage st fully written; stage st^1 readers done

        // ---- prefetch next tile's K/V into registers (latency covered by QK) ----
        {
            const int kn = (kt + 1 < SEQ / BK) ? (k0 + BK) : k0;
            const float* kp = k + ((size_t)b * SEQ + kn + krow) * HD + cb;
            const float* vp = v + ((size_t)b * SEQ + kn + krow) * HD + cb;
#pragma unroll
            for (int j = 0; j < 4; j++) { kx[j] = *(const float4*)(kp + 4 * j);
                                          vx[j] = *(const float4*)(vp + 4 * j); }
        }

        // ---- mask loads ----
        int mA[8], mB[8], mC[8], mD[8];
        if (wide) {
            const int* mi = (const int*)mask;
#pragma unroll
            for (int T = 0; T < 8; T++) {
                const int2 u = *(const int2*)(mi + mrow_lo_base + k0 + 8 * T);
                const int2 w = *(const int2*)(mi + mrow_hi_base + k0 + 8 * T);
                mA[T] = u.x; mB[T] = u.y; mC[T] = w.x; mD[T] = w.y;
            }
        } else {
#pragma unroll
            for (int T = 0; T < 8; T++) {
                const uchar2 u = *(const uchar2*)(mask + mrow_lo_base + k0 + 8 * T);
                const uchar2 w = *(const uchar2*)(mask + mrow_hi_base + k0 + 8 * T);
                mA[T] = u.x; mB[T] = u.y; mC[T] = w.x; mD[T] = w.y;
            }
        }

        // ---- S = Q K^T via 3x split-bf16 mma, frags via ldmatrix.x4 ----
        float sacc[8][4];
#pragma unroll
        for (int T = 0; T < 8; T++)
#pragma unroll
            for (int r = 0; r < 4; r++) sacc[T][r] = 0.f;

#pragma unroll
        for (int s = 0; s < 4; s++) {
#pragma unroll
            for (int tp = 0; tp < 4; tp++) {
                const unsigned off = (unsigned)(tp * (16 * LDB * 2) + s * 32);
                unsigned h0a, h1a, h0b, h1b, l0a, l1a, l0b, l1b;
                ldsm4(h0a, h1a, h0b, h1b, khi_b + off);
                ldsm4(l0a, l1a, l0b, l1b, klo_b + off);
                mma_bf16(sacc[2 * tp],     qh[s], h0a, h1a);
                mma_bf16(sacc[2 * tp],     qh[s], l0a, l1a);
                mma_bf16(sacc[2 * tp],     ql[s], h0a, h1a);
                mma_bf16(sacc[2 * tp + 1], qh[s], h0b, h1b);
                mma_bf16(sacc[2 * tp + 1], qh[s], l0b, l1b);
                mma_bf16(sacc[2 * tp + 1], ql[s], h0b, h1b);
            }
        }

        // ---- scale (1/8) + mask (True -> 1e-9) ----
#pragma unroll
        for (int T = 0; T < 8; T++) {
            sacc[T][0] = mA[T] ? 1e-9f : sacc[T][0] * 0.125f;
            sacc[T][1] = mB[T] ? 1e-9f : sacc[T][1] * 0.125f;
            sacc[T][2] = mC[T] ? 1e-9f : sacc[T][2] * 0.125f;
            sacc[T][3] = mD[T] ? 1e-9f : sacc[T][3] * 0.125f;
        }

        // ---- online softmax (row stats across the 4-lane quad) ----
        float tmx_lo = sacc[0][0], tmx_hi = sacc[0][2];
#pragma unroll
        for (int T = 0; T < 8; T++) {
            tmx_lo = fmaxf(tmx_lo, fmaxf(sacc[T][0], sacc[T][1]));
            tmx_hi = fmaxf(tmx_hi, fmaxf(sacc[T][2], sacc[T][3]));
        }
#pragma unroll
        for (int off = 1; off < 4; off <<= 1) {
            tmx_lo = fmaxf(tmx_lo, __shfl_xor_sync(0xffffffffu, tmx_lo, off));
            tmx_hi = fmaxf(tmx_hi, __shfl_xor_sync(0xffffffffu, tmx_hi, off));
        }

        const float mn_lo = fmaxf(mr_lo, tmx_lo);
        const float mn_hi = fmaxf(mr_hi, tmx_hi);
        const float cr_lo = __expf(mr_lo - mn_lo);
        const float cr_hi = __expf(mr_hi - mn_hi);
        mr_lo = mn_lo; mr_hi = mn_hi;

#pragma unroll
        for (int t = 0; t < 8; t++) {
            o[t][0] *= cr_lo; o[t][1] *= cr_lo;
            o[t][2] *= cr_hi; o[t][3] *= cr_hi;
        }

        float sum_lo = 0.f, sum_hi = 0.f;
        unsigned phA[8], phB[8], plA[8], plB[8];
#pragma unroll
        for (int T = 0; T < 8; T++) {
            const float p0 = __expf(sacc[T][0] - mn_lo);
            const float p1 = __expf(sacc[T][1] - mn_lo);
            const float p2 = __expf(sacc[T][2] - mn_hi);
            const float p3 = __expf(sacc[T][3] - mn_hi);
            sum_lo += p0 + p1;
            sum_hi += p2 + p3;
            split2(p0, p1, phA[T], plA[T]);
            split2(p2, p3, phB[T], plB[T]);
        }
#pragma unroll
        for (int off = 1; off < 4; off <<= 1) {
            sum_lo += __shfl_xor_sync(0xffffffffu, sum_lo, off);
            sum_hi += __shfl_xor_sync(0xffffffffu, sum_hi, off);
        }
        l_lo = l_lo * cr_lo + sum_lo;
        l_hi = l_hi * cr_hi + sum_hi;

        // ---- store next tile into the other stage (no sync needed here) ----
        store_tile(st ^ 1, kx, vx);

        // ---- O += P V via 3x split-bf16 mma, V frags via ldmatrix.x4.trans ----
#pragma unroll
        for (int s = 0; s < 4; s++) {
            const unsigned ah[4] = {phA[2 * s], phB[2 * s], phA[2 * s + 1], phB[2 * s + 1]};
            const unsigned al[4] = {plA[2 * s], plB[2 * s], plA[2 * s + 1], plB[2 * s + 1]};
#pragma unroll
            for (int tp = 0; tp < 4; tp++) {
                const unsigned off = (unsigned)(s * (16 * LDB * 2) + tp * 32);
                unsigned h0a, h1a, h0b, h1b, l0a, l1a, l0b, l1b;
                ldsm4t(h0a, h1a, h0b, h1b, vhi_b + off);
                ldsm4t(l0a, l1a, l0b, l1b, vlo_b + off);
                mma_bf16(o[2 * tp],     ah, h0a, h1a);
                mma_bf16(o[2 * tp],     ah, l0a, l1a);
                mma_bf16(o[2 * tp],     al, h0a, h1a);
                mma_bf16(o[2 * tp + 1], ah, h0b, h1b);
                mma_bf16(o[2 * tp + 1], ah, l0b, l1b);
                mma_bf16(o[2 * tp + 1], al, h0b, h1b);
            }
        }
    }

    // ---- epilogue: normalize and store ----
    const float inv_lo = 1.f / l_lo;
    const float inv_hi = 1.f / l_hi;
    float* olo_p = out + ((size_t)b * SEQ + q0 + row_lo) * HD;
    float* ohi_p = olo_p + 8 * HD;
#pragma unroll
    for (int t = 0; t < 8; t++) {
        *(float2*)(olo_p + 8 * t + 2 * c) = make_float2(o[t][0] * inv_lo, o[t][1] * inv_lo);
        *(float2*)(ohi_p + 8 * t + 2 * c) = make_float2(o[t][2] * inv_hi, o[t][3] * inv_hi);
    }
}

extern "C" void kernel_launch(void* const* d_in, const int* in_sizes, int n_in,
                              void* d_out, int out_size)
{
    (void)out_size;
    int mask_idx = -1;
    for (int i = 0; i < n_in; i++)
        if ((long long)in_sizes[i] == MASK_ELEMS) { mask_idx = i; break; }
    if (mask_idx < 0) mask_idx = 3;

    const float* qkv[3];
    int nq = 0;
    for (int i = 0; i < n_in && nq < 3; i++)
        if (i != mask_idx) qkv[nq++] = (const float*)d_in[i];

    const float* q = qkv[0];
    const float* k = qkv[1];
    const float* v = qkv[2];
    const unsigned char* mask = (const unsigned char*)d_in[mask_idx];
    float* out = (float*)d_out;

    cudaFuncSetAttribute(attn_kernel, cudaFuncAttributeMaxDynamicSharedMemorySize,
                         (int)SMEM_BYTES);

    detect_mask_kernel<<<1, 32>>>(mask);

    dim3 grid(SEQ / BQ, BATCH);
    attn_kernel<<<grid, THREADS, SMEM_BYTES>>>(q, k, v, mask, out);
}